// round 3
// baseline (speedup 1.0000x reference)
#include <cuda_runtime.h>

// Problem constants (fixed shapes from reference)
#define TSTEPS   512
#define H        32
#define NB       32     // batch tile per CTA (one per lane)
#define NGO      16     // gate-groups (threads per batch element)
#define NTHREADS 512    // NB * NGO

// Dynamic smem layout (float offsets); all 16B aligned
#define OFF_W0    0        // 128*64
#define OFF_W1    8192     // 128*64
#define OFF_GS    16384    // 128*32 gates [g][b]
#define OFF_INA   20480    // 32 kp * 32 b * 2 floats (float2 [kp][b]) layer0 input [x; h0]
#define OFF_INB   24576    // layer1 input [h0; h1]
#define OFF_BIAS0 28672    // 128
#define OFF_BIAS1 28800    // 128
#define OFF_W1S   28928    // 32
#define OFF_B1S   28960    // 32
#define OFF_W2S   28992    // 64
#define SMEM_FLOATS 29056
#define SMEM_BYTES  (SMEM_FLOATS * 4)

__device__ __forceinline__ void upk2(unsigned long long v, float& lo, float& hi) {
    asm("mov.b64 {%0,%1}, %2;" : "=f"(lo), "=f"(hi) : "l"(v));
}
// packed fp32x2 FMA: d.lo += a.lo*b.lo ; d.hi += a.hi*b.hi
__device__ __forceinline__ void ffma2(unsigned long long& d, unsigned long long a, unsigned long long b) {
    asm("fma.rn.f32x2 %0, %1, %2, %0;" : "+l"(d) : "l"(a), "l"(b));
}
__device__ __forceinline__ float sigm(float v) {
    float e = __expf(-v);
    return __fdividef(1.0f, 1.0f + e);
}
__device__ __forceinline__ float tanh_(float v) {
    float e = __expf(-2.0f * v);
    return __fdividef(2.0f, 1.0f + e) - 1.0f;
}

// Compute 8 gates (rows [8*go, 8*go+8)) for batch lane b from K=64 input in inX.
// Weights: Ws row-major [128][64], read as broadcast LDS.128.
// Inputs: inX is float2 [32 kp][32 b], read as LDS.64.
__device__ __forceinline__ void gate_phase(const float* __restrict__ Ws,
                                           const float* __restrict__ inX,
                                           const float* __restrict__ bias,
                                           float* __restrict__ gs,
                                           int go, int b) {
    unsigned long long acc[8];
#pragma unroll
    for (int j = 0; j < 8; j++) acc[j] = 0ull;
    const unsigned long long* ip = (const unsigned long long*)inX;  // [kp*NB + b]
#pragma unroll
    for (int kq = 0; kq < 16; kq++) {
        unsigned long long i01 = ip[(2 * kq + 0) * NB + b];
        unsigned long long i23 = ip[(2 * kq + 1) * NB + b];
#pragma unroll
        for (int j = 0; j < 8; j++) {
            ulonglong2 w = *(const ulonglong2*)(Ws + (8 * go + j) * 64 + kq * 4);
            ffma2(acc[j], w.x, i01);
            ffma2(acc[j], w.y, i23);
        }
    }
#pragma unroll
    for (int j = 0; j < 8; j++) {
        float lo, hi;
        upk2(acc[j], lo, hi);
        gs[(8 * go + j) * NB + b] = lo + hi + bias[8 * go + j];
    }
}

// Update h/c for j0=2*go, j0+1 from gates in gs [g][b]. PyTorch order: i,f,g,o.
__device__ __forceinline__ void update_phase(const float* __restrict__ gs,
                                             int go, int b,
                                             float& ca, float& cb,
                                             float& ha, float& hb) {
    int j0 = 2 * go;
    {
        float iv = sigm(gs[(0 * H + j0) * NB + b]);
        float fv = sigm(gs[(1 * H + j0) * NB + b]);
        float gv = tanh_(gs[(2 * H + j0) * NB + b]);
        float ov = sigm(gs[(3 * H + j0) * NB + b]);
        ca = fv * ca + iv * gv;
        ha = ov * tanh_(ca);
    }
    {
        int j1 = j0 + 1;
        float iv = sigm(gs[(0 * H + j1) * NB + b]);
        float fv = sigm(gs[(1 * H + j1) * NB + b]);
        float gv = tanh_(gs[(2 * H + j1) * NB + b]);
        float ov = sigm(gs[(3 * H + j1) * NB + b]);
        cb = fv * cb + iv * gv;
        hb = ov * tanh_(cb);
    }
}

__global__ void __launch_bounds__(NTHREADS, 1)
lstm_fused_kernel(const float* __restrict__ tensor,
                  const float* __restrict__ w1,   const float* __restrict__ b1,
                  const float* __restrict__ Wih0, const float* __restrict__ Whh0,
                  const float* __restrict__ bih0, const float* __restrict__ bhh0,
                  const float* __restrict__ Wih1, const float* __restrict__ Whh1,
                  const float* __restrict__ bih1, const float* __restrict__ bhh1,
                  const float* __restrict__ w2,   const float* __restrict__ b2,
                  float* __restrict__ out) {
    extern __shared__ float smem[];
    float* W0s   = smem + OFF_W0;
    float* W1s   = smem + OFF_W1;
    float* gs    = smem + OFF_GS;
    float* inA   = smem + OFF_INA;
    float* inB   = smem + OFF_INB;
    float* bias0 = smem + OFF_BIAS0;
    float* bias1 = smem + OFF_BIAS1;
    float* w1s   = smem + OFF_W1S;
    float* b1s   = smem + OFF_B1S;
    float* w2s   = smem + OFF_W2S;

    const int tid = threadIdx.x;
    const int b   = tid & (NB - 1);   // batch lane
    const int go  = tid >> 5;         // gate group / j-pair owner

    // ---- Preload weights into SMEM (combined [Wih | Whh] rows, K=64) ----
    for (int idx = tid; idx < 128 * 32; idx += NTHREADS) {
        int g = idx >> 5, k = idx & 31;
        W0s[g * 64 + k]      = Wih0[idx];
        W0s[g * 64 + 32 + k] = Whh0[idx];
        W1s[g * 64 + k]      = Wih1[idx];
        W1s[g * 64 + 32 + k] = Whh1[idx];
    }
    for (int idx = tid; idx < 128; idx += NTHREADS) {
        bias0[idx] = bih0[idx] + bhh0[idx];
        bias1[idx] = bih1[idx] + bhh1[idx];
    }
    if (tid < 32) { w1s[tid] = w1[tid]; b1s[tid] = b1[tid]; }
    if (tid < 64) { w2s[tid] = w2[tid]; }

    // ---- Zero initial hidden states in staging buffers ----
    *(float2*)&inA[((16 + go) * NB + b) * 2] = make_float2(0.f, 0.f);
    *(float2*)&inB[((go)      * NB + b) * 2] = make_float2(0.f, 0.f);
    *(float2*)&inB[((16 + go) * NB + b) * 2] = make_float2(0.f, 0.f);
    float c0a = 0.f, c0b = 0.f, c1a = 0.f, c1b = 0.f;
    __syncthreads();

    const int bg = blockIdx.x * NB + b;           // global batch index
    const float* __restrict__ seq = tensor + (long)bg * TSTEPS;

    for (int t = 0; t < TSTEPS; t++) {
        // x = relu(s * w1 + b1) for this thread's two j slots
        float s  = seq[t];
        float xa = fmaxf(fmaf(s, w1s[2 * go + 0], b1s[2 * go + 0]), 0.f);
        float xb = fmaxf(fmaf(s, w1s[2 * go + 1], b1s[2 * go + 1]), 0.f);
        *(float2*)&inA[(go * NB + b) * 2] = make_float2(xa, xb);
        __syncthreads();                               // S1: inA[x] ready

        gate_phase(W0s, inA, bias0, gs, go, b);        // layer0 gates from [x; h0]
        __syncthreads();                               // S2: gates0 ready

        float ha, hb;
        update_phase(gs, go, b, c0a, c0b, ha, hb);     // h0', c0'
        float2 h0p = make_float2(ha, hb);
        *(float2*)&inA[((16 + go) * NB + b) * 2] = h0p;  // h0 for next step's layer0
        *(float2*)&inB[((go)      * NB + b) * 2] = h0p;  // h0 as layer1 input
        __syncthreads();                               // S3: inB[h0] ready

        gate_phase(W1s, inB, bias1, gs, go, b);        // layer1 gates from [h0; h1]
        __syncthreads();                               // S4: gates1 ready

        update_phase(gs, go, b, c1a, c1b, ha, hb);     // h1', c1'
        *(float2*)&inB[((16 + go) * NB + b) * 2] = make_float2(ha, hb);
        __syncthreads();                               // S5: inB[h1] ready for next step
    }

    // ---- Head: out[b] = [h0_final ; h1_final] . w2 + b2 ----
    if (go == 0) {
        unsigned long long acc = 0ull;
        const unsigned long long* ip = (const unsigned long long*)inB;
        const unsigned long long* wp = (const unsigned long long*)w2s;
#pragma unroll
        for (int kp = 0; kp < 32; kp++) {
            ffma2(acc, wp[kp], ip[kp * NB + b]);
        }
        float lo, hi;
        upk2(acc, lo, hi);
        out[bg] = lo + hi + b2[0];
    }
}

extern "C" void kernel_launch(void* const* d_in, const int* in_sizes, int n_in,
                              void* d_out, int out_size) {
    const float* tensor = (const float*)d_in[0];
    const float* w1     = (const float*)d_in[1];
    const float* b1     = (const float*)d_in[2];
    const float* Wih0   = (const float*)d_in[3];
    const float* Whh0   = (const float*)d_in[4];
    const float* bih0   = (const float*)d_in[5];
    const float* bhh0   = (const float*)d_in[6];
    const float* Wih1   = (const float*)d_in[7];
    const float* Whh1   = (const float*)d_in[8];
    const float* bih1   = (const float*)d_in[9];
    const float* bhh1   = (const float*)d_in[10];
    const float* w2     = (const float*)d_in[11];
    const float* b2     = (const float*)d_in[12];
    float* out = (float*)d_out;

    int Btot = in_sizes[0] / TSTEPS;       // 4096 (IN=1)
    int grid = (Btot + NB - 1) / NB;       // 128 CTAs

    cudaFuncSetAttribute(lstm_fused_kernel,
                         cudaFuncAttributeMaxDynamicSharedMemorySize, SMEM_BYTES);
    lstm_fused_kernel<<<grid, NTHREADS, SMEM_BYTES>>>(
        tensor, w1, b1, Wih0, Whh0, bih0, bhh0,
        Wih1, Whh1, bih1, bhh1, w2, b2, out);
}